// round 1
// baseline (speedup 1.0000x reference)
#include <cuda_runtime.h>
#include <cuda_bf16.h>
#include <cstdint>

// Problem constants (fixed by the reference setup_inputs)
#define N_USERS_C 200000
#define N_ITEMS_C 100000
#define NN_C      300000          // N_USERS + N_ITEMS
#define D_C       64
#define NEDGES_C  1200000

// Scratch accumulator: zero-initialized at module load. The finalize kernel
// restores it to zero every run, so each graph replay sees a clean state.
__device__ float g_agg[(size_t)NN_C * D_C];
// 1 if filt != identity (general matmul path needed). Written every run.
__device__ int g_general;

// ---------------------------------------------------------------------------
// K0: check whether filt == eye(64). One block. Writes g_general each run.
// ---------------------------------------------------------------------------
__global__ void k_check_filt(const float* __restrict__ filt) {
    __shared__ int s_bad;
    if (threadIdx.x == 0) s_bad = 0;
    __syncthreads();
    int bad = 0;
    for (int i = threadIdx.x; i < D_C * D_C; i += blockDim.x) {
        int r = i >> 6, c = i & 63;
        float expect = (r == c) ? 1.0f : 0.0f;
        if (filt[i] != expect) bad = 1;
    }
    if (bad) atomicOr(&s_bad, 1);
    __syncthreads();
    if (threadIdx.x == 0) g_general = s_bad;
}

// ---------------------------------------------------------------------------
// K1: edge scatter. 16 threads per edge; each thread handles one float4
// (16 B) of the 256 B row, gathered from emb[col], scaled by val, and
// reduced into g_agg[row] with a vector red (no return -> REDG path).
// ---------------------------------------------------------------------------
__device__ __forceinline__ void red_add_v4(float* addr, float4 v) {
    asm volatile("red.global.add.v4.f32 [%0], {%1, %2, %3, %4};"
                 :: "l"(addr), "f"(v.x), "f"(v.y), "f"(v.z), "f"(v.w)
                 : "memory");
}

__global__ void __launch_bounds__(256, 8)
k_scatter(const int* __restrict__ adj_rows,
          const int* __restrict__ adj_cols,
          const float* __restrict__ adj_vals,
          const float* __restrict__ user_emb,
          const float* __restrict__ item_emb) {
    int gtid = blockIdx.x * 256 + threadIdx.x;
    int e = gtid >> 4;          // edge index
    int q = gtid & 15;          // quarter-row slot (float4 index)
    if (e >= NEDGES_C) return;

    int   col = __ldg(&adj_cols[e]);   // broadcast within 16-lane group (1 req)
    int   row = __ldg(&adj_rows[e]);
    float val = __ldg(&adj_vals[e]);

    const float4* src = (col < N_USERS_C)
        ? (const float4*)(user_emb + (size_t)col * D_C)
        : (const float4*)(item_emb + (size_t)(col - N_USERS_C) * D_C);

    float4 v = __ldg(&src[q]);
    v.x *= val; v.y *= val; v.z *= val; v.w *= val;

    red_add_v4(&g_agg[(size_t)row * D_C + q * 4], v);
}

// ---------------------------------------------------------------------------
// K2: finalize. Per row r: read emb row, read+clear agg row,
// t = 2*emb - agg; h = sigmoid(t @ filt)  (fast path: filt == I -> h = sigmoid(t)).
// Write out[r*128 + 0..63] = emb, out[r*128 + 64..127] = h.
// Grid-stride, 4 rows per block per iteration (NN % 4 == 0 -> uniform control).
// ---------------------------------------------------------------------------
__global__ void __launch_bounds__(256)
k_final(const float* __restrict__ user_emb,
        const float* __restrict__ item_emb,
        const float* __restrict__ filt,
        float* __restrict__ out) {
    __shared__ float s_filt[D_C * D_C];   // only populated on the general path
    __shared__ float s_t[4][D_C];

    const int gen = g_general;            // uniform across grid
    if (gen) {
        for (int i = threadIdx.x; i < D_C * D_C; i += blockDim.x)
            s_filt[i] = filt[i];
        __syncthreads();
    }

    const int sub = threadIdx.x >> 6;     // row-group within block (0..3)
    const int j   = threadIdx.x & 63;     // column

    for (int base = blockIdx.x * 4; base < NN_C; base += gridDim.x * 4) {
        int r = base + sub;

        float e = (r < N_USERS_C)
            ? __ldg(&user_emb[(size_t)r * D_C + j])
            : __ldg(&item_emb[(size_t)(r - N_USERS_C) * D_C + j]);

        size_t aidx = (size_t)r * D_C + j;
        float a = g_agg[aidx];
        g_agg[aidx] = 0.0f;               // restore scratch for next replay

        float t = 2.0f * e - a;
        out[(size_t)r * 128 + j] = e;

        float h;
        if (!gen) {
            h = t;
        } else {
            s_t[sub][j] = t;
            __syncthreads();
            float acc = 0.0f;
            #pragma unroll 8
            for (int k = 0; k < D_C; k++)
                acc = fmaf(s_t[sub][k], s_filt[k * D_C + j], acc);
            h = acc;
            __syncthreads();
        }
        out[(size_t)r * 128 + 64 + j] = 1.0f / (1.0f + __expf(-h));
    }
}

// ---------------------------------------------------------------------------
// Launch. Inputs (metadata order):
//   0: adj_rows (int32, 1.2M)   1: adj_cols (int32, 1.2M)
//   2: adj_vals (f32, 1.2M)     3: user_emb (f32, 200000*64)
//   4: item_emb (f32, 100000*64) 5: filt (f32, 64*64)
// Output: 300000*128 f32 = rows of [emb | h], users first then items.
// ---------------------------------------------------------------------------
extern "C" void kernel_launch(void* const* d_in, const int* in_sizes, int n_in,
                              void* d_out, int out_size) {
    const int*   adj_rows = (const int*)  d_in[0];
    const int*   adj_cols = (const int*)  d_in[1];
    const float* adj_vals = (const float*)d_in[2];
    const float* user_emb = (const float*)d_in[3];
    const float* item_emb = (const float*)d_in[4];
    const float* filt     = (const float*)d_in[5];
    float* out = (float*)d_out;

    k_check_filt<<<1, 256>>>(filt);

    int scatter_blocks = (NEDGES_C * 16 + 255) / 256;   // 75000
    k_scatter<<<scatter_blocks, 256>>>(adj_rows, adj_cols, adj_vals,
                                       user_emb, item_emb);

    k_final<<<1280, 256>>>(user_emb, item_emb, filt, out);
}

// round 2
// speedup vs baseline: 5.1882x; 5.1882x over previous
#include <cuda_runtime.h>
#include <cuda_bf16.h>
#include <cstdint>

// Problem constants (fixed by the reference setup_inputs)
#define N_USERS_C 200000
#define NN_C      300000          // N_USERS + N_ITEMS
#define D_C       64
#define NEDGES_C  1200000
#define NB1       293             // ceil(NN_C / 1024)

// Scratch (device globals; zero-init at load; counts re-zeroed every replay)
__device__ int  g_counts [NN_C];
__device__ int  g_offsets[NN_C + 1];
__device__ int  g_cursors[NN_C];
__device__ int  g_partials[NB1];
__device__ int2 g_edges  [NEDGES_C];   // (col, bitcast(val)) sorted by row
__device__ int  g_general;             // 1 if filt != eye(64)

// ---------------------------------------------------------------------------
// K0: is filt == eye(64)?  Written fresh every run.
// ---------------------------------------------------------------------------
__global__ void k_check_filt(const float* __restrict__ filt) {
    __shared__ int s_bad;
    if (threadIdx.x == 0) s_bad = 0;
    __syncthreads();
    int bad = 0;
    for (int i = threadIdx.x; i < D_C * D_C; i += blockDim.x) {
        int r = i >> 6, c = i & 63;
        float expect = (r == c) ? 1.0f : 0.0f;
        if (filt[i] != expect) bad = 1;
    }
    if (bad) atomicOr(&s_bad, 1);
    __syncthreads();
    if (threadIdx.x == 0) g_general = s_bad;
}

// ---------------------------------------------------------------------------
// K1: per-row edge histogram (int atomics, spread over 300K addresses)
// ---------------------------------------------------------------------------
__global__ void __launch_bounds__(256)
k_hist(const int* __restrict__ adj_rows) {
    int e = blockIdx.x * 256 + threadIdx.x;
    if (e < NEDGES_C) atomicAdd(&g_counts[adj_rows[e]], 1);
}

// ---------------------------------------------------------------------------
// K2: block-level exclusive scan of counts; emits block totals; zeroes counts
//     (so the next graph replay starts clean).
// ---------------------------------------------------------------------------
__global__ void __launch_bounds__(1024)
k_scan1() {
    __shared__ int s[1024];
    int idx = blockIdx.x * 1024 + threadIdx.x;
    int v = (idx < NN_C) ? g_counts[idx] : 0;
    if (idx < NN_C) g_counts[idx] = 0;
    s[threadIdx.x] = v;
    __syncthreads();
    #pragma unroll
    for (int d = 1; d < 1024; d <<= 1) {
        int add = (threadIdx.x >= d) ? s[threadIdx.x - d] : 0;
        __syncthreads();
        s[threadIdx.x] += add;
        __syncthreads();
    }
    int incl = s[threadIdx.x];
    if (idx < NN_C) g_offsets[idx] = incl - v;          // block-local exclusive
    if (threadIdx.x == 1023) g_partials[blockIdx.x] = incl;
}

// K3: exclusive scan of the 293 block totals (single block)
__global__ void __launch_bounds__(512)
k_scan2() {
    __shared__ int s[512];
    int t = threadIdx.x;
    int v = (t < NB1) ? g_partials[t] : 0;
    s[t] = v;
    __syncthreads();
    #pragma unroll
    for (int d = 1; d < 512; d <<= 1) {
        int add = (t >= d) ? s[t - d] : 0;
        __syncthreads();
        s[t] += add;
        __syncthreads();
    }
    if (t < NB1) g_partials[t] = s[t] - v;              // exclusive
}

// K4: add block offsets; materialize cursors; cap offsets[N]
__global__ void __launch_bounds__(1024)
k_scan3() {
    int idx = blockIdx.x * 1024 + threadIdx.x;
    if (idx < NN_C) {
        int off = g_offsets[idx] + g_partials[blockIdx.x];
        g_offsets[idx] = off;
        g_cursors[idx] = off;
    }
    if (idx == 0) g_offsets[NN_C] = NEDGES_C;
}

// ---------------------------------------------------------------------------
// K5: bucket edges into row-sorted CSR order
// ---------------------------------------------------------------------------
__global__ void __launch_bounds__(256)
k_bucket(const int* __restrict__ adj_rows,
         const int* __restrict__ adj_cols,
         const float* __restrict__ adj_vals) {
    int e = blockIdx.x * 256 + threadIdx.x;
    if (e >= NEDGES_C) return;
    int r = adj_rows[e];
    int pos = atomicAdd(&g_cursors[r], 1);
    g_edges[pos] = make_int2(adj_cols[e], __float_as_int(adj_vals[e]));
}

// ---------------------------------------------------------------------------
// K6: fused segment-sum + finalize. One warp per row; each lane owns 2 cols.
//     agg accumulated in registers -> no f32 atomics anywhere.
// ---------------------------------------------------------------------------
__global__ void __launch_bounds__(256)
k_fused(const float* __restrict__ user_emb,
        const float* __restrict__ item_emb,
        const float* __restrict__ filt,
        float* __restrict__ out) {
    __shared__ float s_filt[D_C * D_C];   // general path only
    __shared__ float s_t[8][D_C];

    const int gen = g_general;            // uniform
    if (gen) {
        for (int i = threadIdx.x; i < D_C * D_C; i += blockDim.x)
            s_filt[i] = filt[i];
        __syncthreads();
    }

    const int w    = threadIdx.x >> 5;    // warp in block (0..7)
    const int lane = threadIdx.x & 31;
    const int r    = blockIdx.x * 8 + w;  // 37500*8 == 300000 exactly

    const int start = g_offsets[r];
    const int end   = g_offsets[r + 1];

    float2 acc = make_float2(0.f, 0.f);
    for (int i = start; i < end; i++) {
        int2 eg = g_edges[i];             // broadcast load (same addr all lanes)
        float val = __int_as_float(eg.y);
        const float2* src = (eg.x < N_USERS_C)
            ? (const float2*)(user_emb + (size_t)eg.x * D_C)
            : (const float2*)(item_emb + (size_t)(eg.x - N_USERS_C) * D_C);
        float2 vv = __ldg(&src[lane]);    // 256B coalesced per warp
        acc.x = fmaf(val, vv.x, acc.x);
        acc.y = fmaf(val, vv.y, acc.y);
    }

    const float2* esrc = (r < N_USERS_C)
        ? (const float2*)(user_emb + (size_t)r * D_C)
        : (const float2*)(item_emb + (size_t)(r - N_USERS_C) * D_C);
    float2 e = __ldg(&esrc[lane]);

    float2 t = make_float2(2.0f * e.x - acc.x, 2.0f * e.y - acc.y);

    float2* orow = (float2*)(out + (size_t)r * 128);
    orow[lane] = e;                       // [0:64) = emb

    float2 h;
    if (!gen) {
        h = t;
    } else {
        s_t[w][2 * lane]     = t.x;
        s_t[w][2 * lane + 1] = t.y;
        __syncwarp();
        float a0 = 0.f, a1 = 0.f;
        #pragma unroll 8
        for (int k = 0; k < D_C; k++) {
            float tk = s_t[w][k];
            a0 = fmaf(tk, s_filt[k * D_C + 2 * lane],     a0);
            a1 = fmaf(tk, s_filt[k * D_C + 2 * lane + 1], a1);
        }
        h = make_float2(a0, a1);
    }
    orow[32 + lane] = make_float2(1.0f / (1.0f + __expf(-h.x)),
                                  1.0f / (1.0f + __expf(-h.y)));
}

// ---------------------------------------------------------------------------
// Launch. Inputs (metadata order):
//   0: adj_rows (i32 1.2M)  1: adj_cols (i32 1.2M)  2: adj_vals (f32 1.2M)
//   3: user_emb (f32 200000*64)  4: item_emb (f32 100000*64)  5: filt (64*64)
// Output: 300000 rows of [emb | h] (f32, 128 wide), users then items.
// ---------------------------------------------------------------------------
extern "C" void kernel_launch(void* const* d_in, const int* in_sizes, int n_in,
                              void* d_out, int out_size) {
    const int*   adj_rows = (const int*)  d_in[0];
    const int*   adj_cols = (const int*)  d_in[1];
    const float* adj_vals = (const float*)d_in[2];
    const float* user_emb = (const float*)d_in[3];
    const float* item_emb = (const float*)d_in[4];
    const float* filt     = (const float*)d_in[5];
    float* out = (float*)d_out;

    const int EB = (NEDGES_C + 255) / 256;   // 4688

    k_check_filt<<<1, 256>>>(filt);
    k_hist     <<<EB, 256>>>(adj_rows);
    k_scan1    <<<NB1, 1024>>>();
    k_scan2    <<<1, 512>>>();
    k_scan3    <<<NB1, 1024>>>();
    k_bucket   <<<EB, 256>>>(adj_rows, adj_cols, adj_vals);
    k_fused    <<<NN_C / 8, 256>>>(user_emb, item_emb, filt, out);
}